// round 9
// baseline (speedup 1.0000x reference)
#include <cuda_runtime.h>
#include <cuda_bf16.h>
#include <math.h>

#define N        4096
#define T        4096
#define WASH     200
#define NBLK     128
#define TPB      1024                // 32 warps -> 8 per SMSP
#define NWARP    (TPB / 32)
#define RPC      (N / NBLK)          // 32 rows per CTA
#define L_CAP    1472                // per-CTA per-lane ELL word capacity
#define ELL_CAP  6291456             // global ELL words

// ---------------- device globals (no allocations allowed) ----------------
__device__ int                g_cnt[N];       // per-row raw max-lane count
__device__ int                g_wpad[N];      // per-row padded width (mult of 4)
__device__ int                g_off[N + 1];   // exclusive prefix (per-lane units)
__device__ unsigned           g_ell[ELL_CAP]; // packed (val & ~127) | j words
__device__ unsigned long long g_xp[2][N];     // packed {tag:32 | f32 bits:32}
__device__ float              g_wv[N];        // wv[mask[i]] = w_out[i]

// ---- prep 1: per-row max per-lane nonzero count (1 warp per row) ---------
__global__ void k_width(const float* __restrict__ w) {
    int r    = blockIdx.x * 8 + (threadIdx.x >> 5);
    int lane = threadIdx.x & 31;
    if (r >= N) return;
    const float* row = w + (size_t)r * N;
    int cnt = 0;
    #pragma unroll 8
    for (int k = 0; k < N / 32; k++) cnt += (row[k * 32 + lane] != 0.0f);
    for (int o = 16; o; o >>= 1) {
        int v = __shfl_xor_sync(~0u, cnt, o);
        cnt = v > cnt ? v : cnt;
    }
    if (lane == 0) g_cnt[r] = cnt;
}

// ---- prep 1b: pad each row's width to a multiple of 4 --------------------
__global__ void k_group() {
    int g = blockIdx.x * blockDim.x + threadIdx.x;
    if (g >= N) return;
    g_wpad[g] = (g_cnt[g] + 3) & ~3;
}

// ---- prep 2: exclusive prefix scan of g_wpad (1 block) -------------------
__global__ void k_scan() {
    __shared__ int sc[1024];
    int i = threadIdx.x;
    int a0 = g_wpad[4 * i + 0];
    int a1 = g_wpad[4 * i + 1];
    int a2 = g_wpad[4 * i + 2];
    int a3 = g_wpad[4 * i + 3];
    int s  = a0 + a1 + a2 + a3;
    sc[i] = s;
    __syncthreads();
    for (int d = 1; d < 1024; d <<= 1) {
        int v   = sc[i];
        int add = (i >= d) ? sc[i - d] : 0;
        __syncthreads();
        sc[i] = v + add;
        __syncthreads();
    }
    int excl = sc[i] - s;
    g_off[4 * i + 0] = excl;
    g_off[4 * i + 1] = excl + a0;
    g_off[4 * i + 2] = excl + a0 + a1;
    g_off[4 * i + 3] = excl + a0 + a1 + a2;
    if (i == 1023) g_off[N] = sc[1023];
}

// ---- prep 3: fill bank-sliced ELL with packed words (1 warp per row) -----
// Element (i, lane) of a row with base b lives at word
//   b*32 + (i>>2)*128 + lane*4 + (i&3).
// Packed word = (round_to_7(bits(val))) | j, where col = 32*j + lane.
__global__ void k_fillell(const float* __restrict__ w) {
    int r    = blockIdx.x * 8 + (threadIdx.x >> 5);
    int lane = threadIdx.x & 31;
    if (r >= N) return;
    const float* row = w + (size_t)r * N;
    int b   = g_off[r];
    int wid = g_off[r + 1] - b;
    unsigned* base = g_ell + (size_t)b * 32;
    int i = 0;
    for (int k = 0; k < N / 32; k++) {
        float v = row[k * 32 + lane];
        if (v != 0.0f) {
            unsigned bits = (__float_as_uint(v) + 64u) & ~127u;
            base[(i >> 2) * 128 + lane * 4 + (i & 3)] = bits | (unsigned)k;
            i++;
        }
    }
    for (; i < wid; i++)
        base[(i >> 2) * 128 + lane * 4 + (i & 3)] = 0u;   // padding: 0 * sx[lane]
}

// ---- prep 4: wv scatter, zero output, zero BOTH tag buffers --------------
// (tag reset is mandatory for graph replays: stale tags would falsely match)
__global__ void k_prep(const float* __restrict__ w_out,
                       const int* __restrict__ mask,
                       float* __restrict__ out, int out_n) {
    int i = blockIdx.x * blockDim.x + threadIdx.x;     // 8192 threads = 2N
    ((unsigned long long*)g_xp)[i] = 0ull;
    if (i < N)     g_wv[mask[i]] = w_out[i];
    if (i < out_n) out[i] = 0.0f;
}

// ---------------- main persistent ESN kernel -----------------------------
__global__ void __launch_bounds__(TPB, 1)
k_esn(const float* __restrict__ u, const float* __restrict__ w_in,
      float* __restrict__ out) {
    extern __shared__ unsigned char smem_raw[];
    unsigned* sell = (unsigned*)smem_raw;                 // L_CAP*32 words
    float*    sx   = (float*)(sell + L_CAP * 32);         // N
    int*      lrp  = (int*)(sx + N);                      // RPC+1 (per-lane units)
    float*    wsum = (float*)(lrp + RPC + 1);             // NWARP

    const int c    = blockIdx.x;
    const int tid  = threadIdx.x;
    const int wid  = tid >> 5;
    const int lane = tid & 31;
    const int row0 = c * RPC;

    const int seg_beg = g_off[row0];
    int seg_pl = g_off[row0 + RPC] - seg_beg;
    if (seg_pl > L_CAP) seg_pl = L_CAP;

    for (int r = tid; r <= RPC; r += TPB) {
        int v = g_off[row0 + r] - seg_beg;
        lrp[r] = v > L_CAP ? L_CAP : v;
    }
    {   // copy ELL segment (16B-aligned: offsets are multiples of 4 per-lane units)
        const uint4* src = (const uint4*)(g_ell + (size_t)seg_beg * 32);
        uint4*       dst = (uint4*)sell;
        int nvec = seg_pl * 8;
        for (int k = tid; k < nvec; k += TPB) dst[k] = src[k];
    }
    for (int j = tid; j < N; j += TPB) sx[j] = 0.0f;
    __syncthreads();

    // per-warp metadata: one row per warp
    const int kb0 = lrp[wid];
    const int kw  = lrp[wid + 1] - kb0;
    const int gr  = row0 + wid;
    const float winr = w_in[gr];
    const float wvr  = g_wv[gr];
    const uint4* pbase = (const uint4*)sell + (size_t)kb0 * 8 + lane;

    for (int t = 0; t < T; ++t) {
        const float ut = __ldg(&u[t]);
        const int buf = (t + 1) & 1;

        const uint4* p0 = pbase;
        float s0 = 0.0f;
        for (int i = 0; i < kw; i += 4) {
            uint4 q0 = *p0; p0 += 32;
            s0 += __uint_as_float(q0.x & 0xFFFFFF80u) * sx[((q0.x & 127u) << 5) + lane];
            s0 += __uint_as_float(q0.y & 0xFFFFFF80u) * sx[((q0.y & 127u) << 5) + lane];
            s0 += __uint_as_float(q0.z & 0xFFFFFF80u) * sx[((q0.z & 127u) << 5) + lane];
            s0 += __uint_as_float(q0.w & 0xFFFFFF80u) * sx[((q0.w & 127u) << 5) + lane];
        }
        #pragma unroll
        for (int o = 16; o; o >>= 1)
            s0 += __shfl_xor_sync(~0u, s0, o);
        if (lane == 0) {
            float xv = tanhf(winr * ut + s0);
            wsum[wid] = wvr * xv;
            // publish value+tag in ONE atomic 8B word (tag implies value)
            unsigned long long pk =
                ((unsigned long long)(unsigned)(t + 1) << 32) | __float_as_uint(xv);
            asm volatile("st.relaxed.gpu.global.u64 [%0], %1;"
                         :: "l"(&g_xp[buf][gr]), "l"(pk) : "memory");
        }

        // poll own 4 rows (one producer CTA) — overlaps in-CTA warp skew
        float4 xin;
        if (t + 1 < T) {
            const unsigned long long* src = g_xp[buf] + (tid << 2);
            const unsigned tg = (unsigned)(t + 1);
            unsigned long long a0, a1, a2, a3;
            while (true) {
                asm volatile("ld.relaxed.gpu.global.u64 %0, [%1];" : "=l"(a0) : "l"(src + 0) : "memory");
                asm volatile("ld.relaxed.gpu.global.u64 %0, [%1];" : "=l"(a1) : "l"(src + 1) : "memory");
                asm volatile("ld.relaxed.gpu.global.u64 %0, [%1];" : "=l"(a2) : "l"(src + 2) : "memory");
                asm volatile("ld.relaxed.gpu.global.u64 %0, [%1];" : "=l"(a3) : "l"(src + 3) : "memory");
                if ((unsigned)(a0 >> 32) == tg && (unsigned)(a1 >> 32) == tg &&
                    (unsigned)(a2 >> 32) == tg && (unsigned)(a3 >> 32) == tg)
                    break;
                __nanosleep(64);
            }
            xin.x = __uint_as_float((unsigned)a0);
            xin.y = __uint_as_float((unsigned)a1);
            xin.z = __uint_as_float((unsigned)a2);
            xin.w = __uint_as_float((unsigned)a3);
        }
        __syncthreads();   // all gathers of old sx done; wsum complete

        if (t + 1 < T)
            ((float4*)sx)[tid] = xin;                    // install new x
        if (tid == 0 && t >= WASH) {
            float ys = 0.0f;
            #pragma unroll
            for (int w = 0; w < NWARP; w++) ys += wsum[w];
            atomicAdd(&out[t - WASH], ys);               // off-critical-path
        }
        __syncthreads();   // sx ready for next iteration
    }
}

// ---------------- launch ---------------------------------------------------
extern "C" void kernel_launch(void* const* d_in, const int* in_sizes, int n_in,
                              void* d_out, int out_size) {
    const float* u     = (const float*)d_in[0];
    const float* w_res = (const float*)d_in[1];
    const float* w_in  = (const float*)d_in[2];
    const float* w_out = (const float*)d_in[3];
    const int*   mask  = (const int*)d_in[4];
    float*       out   = (float*)d_out;

    const int smem_main = L_CAP * 32 * 4 + N * 4 + (RPC + 1) * 4 + NWARP * 4;
    cudaFuncSetAttribute(k_esn, cudaFuncAttributeMaxDynamicSharedMemorySize, smem_main);

    const int rows_grid = (N + 7) / 8;   // 1 warp per row, 8 warps per block
    k_width<<<rows_grid, 256>>>(w_res);
    k_group<<<(N + 255) / 256, 256>>>();
    k_scan<<<1, 1024>>>();
    k_fillell<<<rows_grid, 256>>>(w_res);
    k_prep<<<(2 * N + 255) / 256, 256>>>(w_out, mask, out, out_size);
    k_esn<<<NBLK, TPB, smem_main>>>(u, w_in, out);
}

// round 10
// speedup vs baseline: 3.3751x; 3.3751x over previous
#include <cuda_runtime.h>
#include <cuda_bf16.h>
#include <math.h>

#define N        4096
#define T        4096
#define WASH     200
#define NBLK     148                 // 1 CTA per SM (GB300: 152 SMs, B300: 148)
#define TPB      896                 // 28 warps: covers max 28 rows/CTA
#define NWARP    (TPB / 32)
#define MAXRPC   28                  // ceil(N / NBLK)
#define L_CAP    1280                // per-CTA per-lane ELL word capacity
#define ELL_CAP  6291456             // global ELL words

// ---------------- device globals (no allocations allowed) ----------------
__device__ int      g_cnt[N];         // per-row raw max-lane count
__device__ int      g_wpad[N];        // per-row padded width (mult of 4)
__device__ int      g_off[N + 1];     // exclusive prefix (per-lane units)
__device__ unsigned g_ell[ELL_CAP];   // packed (val & ~127) | j words
__device__ float    g_x[2][N];
__device__ float    g_wv[N];          // wv[mask[i]] = w_out[i]
__device__ unsigned g_bar;            // monotonic barrier counter

// ---- prep 1: per-row max per-lane nonzero count (1 warp per row) ---------
__global__ void k_width(const float* __restrict__ w) {
    int r    = blockIdx.x * 8 + (threadIdx.x >> 5);
    int lane = threadIdx.x & 31;
    if (r >= N) return;
    const float* row = w + (size_t)r * N;
    int cnt = 0;
    #pragma unroll 8
    for (int k = 0; k < N / 32; k++) cnt += (row[k * 32 + lane] != 0.0f);
    for (int o = 16; o; o >>= 1) {
        int v = __shfl_xor_sync(~0u, cnt, o);
        cnt = v > cnt ? v : cnt;
    }
    if (lane == 0) g_cnt[r] = cnt;
}

// ---- prep 1b: pad each row's width to a multiple of 4 --------------------
__global__ void k_group() {
    int g = blockIdx.x * blockDim.x + threadIdx.x;
    if (g >= N) return;
    g_wpad[g] = (g_cnt[g] + 3) & ~3;
}

// ---- prep 2: exclusive prefix scan of g_wpad (1 block) -------------------
__global__ void k_scan() {
    __shared__ int sc[1024];
    int i = threadIdx.x;
    int a0 = g_wpad[4 * i + 0];
    int a1 = g_wpad[4 * i + 1];
    int a2 = g_wpad[4 * i + 2];
    int a3 = g_wpad[4 * i + 3];
    int s  = a0 + a1 + a2 + a3;
    sc[i] = s;
    __syncthreads();
    for (int d = 1; d < 1024; d <<= 1) {
        int v   = sc[i];
        int add = (i >= d) ? sc[i - d] : 0;
        __syncthreads();
        sc[i] = v + add;
        __syncthreads();
    }
    int excl = sc[i] - s;
    g_off[4 * i + 0] = excl;
    g_off[4 * i + 1] = excl + a0;
    g_off[4 * i + 2] = excl + a0 + a1;
    g_off[4 * i + 3] = excl + a0 + a1 + a2;
    if (i == 1023) g_off[N] = sc[1023];
}

// ---- prep 3: fill bank-sliced ELL with packed words (1 warp per row) -----
// Element (i, lane) of a row with base b lives at word
//   b*32 + (i>>2)*128 + lane*4 + (i&3).
// Packed word = (round_to_7(bits(val))) | j, where col = 32*j + lane.
__global__ void k_fillell(const float* __restrict__ w) {
    int r    = blockIdx.x * 8 + (threadIdx.x >> 5);
    int lane = threadIdx.x & 31;
    if (r >= N) return;
    const float* row = w + (size_t)r * N;
    int b   = g_off[r];
    int wid = g_off[r + 1] - b;
    unsigned* base = g_ell + (size_t)b * 32;
    int i = 0;
    for (int k = 0; k < N / 32; k++) {
        float v = row[k * 32 + lane];
        if (v != 0.0f) {
            unsigned bits = (__float_as_uint(v) + 64u) & ~127u;
            base[(i >> 2) * 128 + lane * 4 + (i & 3)] = bits | (unsigned)k;
            i++;
        }
    }
    for (; i < wid; i++)
        base[(i >> 2) * 128 + lane * 4 + (i & 3)] = 0u;   // padding: 0 * sx[lane]
}

// ---- prep 4: wv scatter, zero output, reset barrier ----------------------
__global__ void k_prep(const float* __restrict__ w_out,
                       const int* __restrict__ mask,
                       float* __restrict__ out, int out_n) {
    int i = blockIdx.x * blockDim.x + threadIdx.x;
    if (i < N)     g_wv[mask[i]] = w_out[i];
    if (i < out_n) out[i] = 0.0f;
    if (i == 0)    g_bar = 0u;
}

// ---------------- main persistent ESN kernel -----------------------------
__global__ void __launch_bounds__(TPB, 1)
k_esn(const float* __restrict__ u, const float* __restrict__ w_in,
      float* __restrict__ out) {
    extern __shared__ unsigned char smem_raw[];
    unsigned* sell = (unsigned*)smem_raw;                 // L_CAP*32 words
    float*    sx   = (float*)(sell + L_CAP * 32);         // N
    int*      lrp  = (int*)(sx + N);                      // MAXRPC+1
    float*    wsum = (float*)(lrp + MAXRPC + 1);          // NWARP

    const int c    = blockIdx.x;
    const int tid  = threadIdx.x;
    const int wid  = tid >> 5;
    const int lane = tid & 31;
    const int row0   = (c * N) / NBLK;
    const int nrows  = ((c + 1) * N) / NBLK - row0;       // 27 or 28

    const int seg_beg = g_off[row0];
    int seg_pl = g_off[row0 + nrows] - seg_beg;
    if (seg_pl > L_CAP) seg_pl = L_CAP;

    for (int r = tid; r <= nrows; r += TPB) {
        int v = g_off[row0 + r] - seg_beg;
        lrp[r] = v > L_CAP ? L_CAP : v;
    }
    {   // copy ELL segment (16B-aligned: offsets are multiples of 4 per-lane units)
        const uint4* src = (const uint4*)(g_ell + (size_t)seg_beg * 32);
        uint4*       dst = (uint4*)sell;
        int nvec = seg_pl * 8;
        for (int k = tid; k < nvec; k += TPB) dst[k] = src[k];
    }
    for (int j = tid; j < N; j += TPB) sx[j] = 0.0f;
    __syncthreads();

    // per-warp metadata: one row per warp (warps >= nrows idle in compute)
    const bool active = (wid < nrows);
    int kb0 = 0, kw = 0, gr = row0;
    float winr = 0.0f, wvr = 0.0f;
    if (active) {
        kb0 = lrp[wid];
        kw  = lrp[wid + 1] - kb0;
        gr  = row0 + wid;
        winr = w_in[gr];
        wvr  = g_wv[gr];
    }
    const uint4* pbase = (const uint4*)sell + (size_t)kb0 * 8 + lane;

    for (int t = 0; t < T; ++t) {
        const float ut = __ldg(&u[t]);
        float* xout = g_x[t & 1];

        if (active) {
            const uint4* p0 = pbase;
            float s0 = 0.0f;
            for (int i = 0; i < kw; i += 4) {
                uint4 q0 = *p0; p0 += 32;
                s0 += __uint_as_float(q0.x & 0xFFFFFF80u) * sx[((q0.x & 127u) << 5) + lane];
                s0 += __uint_as_float(q0.y & 0xFFFFFF80u) * sx[((q0.y & 127u) << 5) + lane];
                s0 += __uint_as_float(q0.z & 0xFFFFFF80u) * sx[((q0.z & 127u) << 5) + lane];
                s0 += __uint_as_float(q0.w & 0xFFFFFF80u) * sx[((q0.w & 127u) << 5) + lane];
            }
            #pragma unroll
            for (int o = 16; o; o >>= 1)
                s0 += __shfl_xor_sync(~0u, s0, o);
            if (lane == 0) {
                float xv = tanhf(winr * ut + s0);
                __stcg(&xout[gr], xv);
                wsum[wid] = wvr * xv;
            }
        }
        __syncthreads();   // orders stcg x-writes before tid0's release below

        if (tid == 0) {
            // release-arrive publishes this CTA's x writes (cumulative release)
            asm volatile("red.release.gpu.global.add.u32 [%0], %1;"
                         :: "l"(&g_bar), "r"(1u) : "memory");
            if (t >= WASH) {          // off-critical-path, overlaps propagation
                float ys = 0.0f;
                for (int w = 0; w < nrows; w++) ys += wsum[w];
                atomicAdd(&out[t - WASH], ys);
            }
            unsigned target = (unsigned)(t + 1) * NBLK;
            unsigned v;
            do {
                asm volatile("ld.acquire.gpu.global.u32 %0, [%1];"
                             : "=r"(v) : "l"(&g_bar) : "memory");
            } while (v < target);
        }
        __syncthreads();

        if (t + 1 < T) {
            const float4* xs4 = (const float4*)xout;
            float4*       sx4 = (float4*)sx;
            for (int idx = tid; idx < N / 4; idx += TPB)
                sx4[idx] = __ldcg(&xs4[idx]);
        }
        __syncthreads();   // RACE FIX: sx reload must complete before next
                           // iteration's gathers read sx
    }
}

// ---------------- launch ---------------------------------------------------
extern "C" void kernel_launch(void* const* d_in, const int* in_sizes, int n_in,
                              void* d_out, int out_size) {
    const float* u     = (const float*)d_in[0];
    const float* w_res = (const float*)d_in[1];
    const float* w_in  = (const float*)d_in[2];
    const float* w_out = (const float*)d_in[3];
    const int*   mask  = (const int*)d_in[4];
    float*       out   = (float*)d_out;

    const int smem_main = L_CAP * 32 * 4 + N * 4 + (MAXRPC + 1) * 4 + NWARP * 4;
    cudaFuncSetAttribute(k_esn, cudaFuncAttributeMaxDynamicSharedMemorySize, smem_main);

    const int rows_grid = (N + 7) / 8;   // 1 warp per row, 8 warps per block
    k_width<<<rows_grid, 256>>>(w_res);
    k_group<<<(N + 255) / 256, 256>>>();
    k_scan<<<1, 1024>>>();
    k_fillell<<<rows_grid, 256>>>(w_res);
    k_prep<<<(N + 255) / 256, 256>>>(w_out, mask, out, out_size);
    k_esn<<<NBLK, TPB, smem_main>>>(u, w_in, out);
}